// round 12
// baseline (speedup 1.0000x reference)
#include <cuda_runtime.h>
#include <cstdint>

#define BB 32
#define TT 64
#define VV 32000
#define EE 512
#define HH 1024
#define GG 4096
#define SS 512
#define KD 1536
#define NSPLIT 8

typedef unsigned long long u64;

// ---- scratch layout (floats) ----
constexpr size_t OFF_WOUT_T  = 0;                                   // [1024][32000]
constexpr size_t OFF_ENCWI_T = OFF_WOUT_T  + (size_t)HH * VV;       // [512][4096]
constexpr size_t OFF_ENCWH_T = OFF_ENCWI_T + (size_t)EE * GG;       // [1024][4096]
constexpr size_t OFF_DECW_T  = OFF_ENCWH_T + (size_t)HH * GG;       // [1536][4096]
constexpr size_t OFF_WS_T    = OFF_DECW_T  + (size_t)KD * GG;       // [1024][512]
constexpr size_t OFF_WO_T    = OFF_WS_T    + (size_t)HH * SS;
constexpr size_t OFF_WC_T    = OFF_WO_T    + (size_t)HH * SS;       // [1024][1024]
constexpr size_t OFF_EMB     = OFF_WC_T    + (size_t)HH * HH;       // [2048][512]
constexpr size_t OFF_ENCX    = OFF_EMB     + (size_t)BB * TT * EE;  // [2048][4096]
constexpr size_t OFF_PART    = OFF_ENCX    + (size_t)BB * TT * GG;  // [8][32][4096]
constexpr size_t OFF_ENCH    = OFF_PART    + (size_t)NSPLIT * BB * GG;
constexpr size_t OFF_ENCC    = OFF_ENCH    + (size_t)BB * HH;
constexpr size_t OFF_DECA    = OFF_ENCC    + (size_t)BB * HH;       // [32][1536] = [emb|h]
constexpr size_t OFF_DECC    = OFF_DECA    + (size_t)BB * KD;
constexpr size_t OFF_HENC    = OFF_DECC    + (size_t)BB * HH;
constexpr size_t OFF_CAT     = OFF_HENC    + (size_t)BB * HH;       // [32][1024]
constexpr size_t OFF_NLL     = OFF_CAT     + (size_t)BB * HH;
constexpr size_t SCRATCH_SZ  = OFF_NLL     + (size_t)BB * TT;

__device__ __align__(16) float g_scratch[SCRATCH_SZ];
__device__ int   g_pred[BB];
__device__ int   g_lastIdx[BB];
__device__ float g_maskSum;

__device__ __forceinline__ u64 fma2(u64 a, u64 b, u64 c) {
    u64 d; asm("fma.rn.f32x2 %0, %1, %2, %3;" : "=l"(d) : "l"(a), "l"(b), "l"(c)); return d;
}
__device__ __forceinline__ u64 pack2(float x, float y) {
    u64 d; asm("mov.b64 %0, {%1, %2};" : "=l"(d) : "f"(x), "f"(y)); return d;
}
__device__ __forceinline__ float2 unpack2(u64 v) {
    float2 r; asm("mov.b64 {%0, %1}, %2;" : "=f"(r.x), "=f"(r.y) : "l"(v)); return r;
}
__device__ __forceinline__ float sigm(float x) { return 1.0f / (1.0f + expf(-x)); }

__global__ void k_prep(const int* __restrict__ s) {
    int b = threadIdx.x;
    int cnt = 0;
    #pragma unroll
    for (int t = 0; t < TT; t++) cnt += (s[b * TT + t] != 0);
    int li = cnt - 1; if (li < 0) li = 0; if (li > TT - 1) li = TT - 1;
    g_lastIdx[b] = li;
    g_pred[b] = 1;
    int tot = cnt;
    #pragma unroll
    for (int o = 16; o; o >>= 1) tot += __shfl_down_sync(0xffffffffu, tot, o);
    if (b == 0) g_maskSum = (float)tot;
}

__global__ void k_init() {
    int i = blockIdx.x * 256 + threadIdx.x;
    if (i < BB * HH) {
        g_scratch[OFF_ENCH + i] = 0.0f;
        g_scratch[OFF_ENCC + i] = 0.0f;
        g_scratch[OFF_DECC + i] = 0.0f;
    }
}

// in[R][C] -> out[C][R]; dims multiples of 32
__global__ void k_transpose(const float* __restrict__ in, float* __restrict__ out, int R, int C) {
    __shared__ float tile[32][33];
    int c0 = blockIdx.x * 32, r0 = blockIdx.y * 32;
    int x = threadIdx.x, y = threadIdx.y;
    #pragma unroll
    for (int j = 0; j < 32; j += 8)
        tile[y + j][x] = in[(size_t)(r0 + y + j) * C + c0 + x];
    __syncthreads();
    #pragma unroll
    for (int j = 0; j < 32; j += 8)
        out[(size_t)(c0 + y + j) * R + r0 + x] = tile[x][y + j];
}

__global__ void k_gather_emb(const int* __restrict__ s, const float* __restrict__ Wemb) {
    int r = blockIdx.x;
    const float4* src = (const float4*)(Wemb + (size_t)s[r] * EE);
    float4* dst = (float4*)(g_scratch + OFF_EMB + (size_t)r * EE);
    dst[threadIdx.x] = src[threadIdx.x];
}

__global__ void k_gather_pred(const float* __restrict__ Wemb) {
    int b = blockIdx.x;
    const float4* src = (const float4*)(Wemb + (size_t)g_pred[b] * EE);
    float4* dst = (float4*)(g_scratch + OFF_DECA + (size_t)b * KD);
    dst[threadIdx.x] = src[threadIdx.x];
}

// out[m][n] = sum_k A[m][k]*Bt[k][n] (+bias). grid: (N/256, Mtiles, splits)
__global__ void __launch_bounds__(256) k_gemm32(
    const float* __restrict__ A, int lda,
    const float* __restrict__ Bt, int ldb,
    float* __restrict__ out, long long ldo,
    int kLen, const float* __restrict__ bias, long long splitPitch)
{
    __shared__ __align__(16) float Asm[32][40];
    const int tid = threadIdx.x;
    const int n = blockIdx.x * 256 + tid;
    A   += (size_t)blockIdx.y * 32 * lda;
    out += (size_t)blockIdx.y * 32 * ldo + (size_t)blockIdx.z * splitPitch;
    const int kbeg = blockIdx.z * kLen;

    u64 acc[16];
    #pragma unroll
    for (int i = 0; i < 16; i++) acc[i] = 0ull;

    const int m  = tid & 31;
    const int kq = (tid >> 5) << 2;

    for (int kt = 0; kt < kLen; kt += 32) {
        float4 av = *(const float4*)(A + (size_t)m * lda + (kbeg + kt + kq));
        __syncthreads();
        Asm[kq + 0][m] = av.x; Asm[kq + 1][m] = av.y;
        Asm[kq + 2][m] = av.z; Asm[kq + 3][m] = av.w;
        __syncthreads();
        const float* bp = Bt + (size_t)(kbeg + kt) * ldb + n;
        #pragma unroll 8
        for (int kk = 0; kk < 32; kk++) {
            float bv = bp[(size_t)kk * ldb];
            u64 b2 = pack2(bv, bv);
            const ulonglong2* ar = (const ulonglong2*)(&Asm[kk][0]);
            #pragma unroll
            for (int q = 0; q < 8; q++) {
                ulonglong2 a2 = ar[q];
                acc[2 * q]     = fma2(a2.x, b2, acc[2 * q]);
                acc[2 * q + 1] = fma2(a2.y, b2, acc[2 * q + 1]);
            }
        }
    }
    float bv = bias ? bias[n] : 0.0f;
    #pragma unroll
    for (int mp = 0; mp < 16; mp++) {
        float2 r = unpack2(acc[mp]);
        out[(size_t)(2 * mp)     * ldo + n] = r.x + bv;
        out[(size_t)(2 * mp + 1) * ldo + n] = r.y + bv;
    }
}

__global__ void k_enc_combine(int t) {
    int i = blockIdx.x * 256 + threadIdx.x;
    int b = i >> 10, j = i & (HH - 1);
    float g[4];
    #pragma unroll
    for (int q = 0; q < 4; q++) {
        int gi = b * GG + q * HH + j;
        float v = g_scratch[OFF_ENCX + (size_t)(b * TT + t) * GG + q * HH + j];
        #pragma unroll
        for (int s = 0; s < NSPLIT; s++) v += g_scratch[OFF_PART + (size_t)s * BB * GG + gi];
        g[q] = v;
    }
    float c = g_scratch[OFF_ENCC + i];
    c = sigm(g[1]) * c + sigm(g[0]) * tanhf(g[2]);
    g_scratch[OFF_ENCC + i] = c;
    float h = sigm(g[3]) * tanhf(c);
    g_scratch[OFF_ENCH + i] = h;
    if (t == g_lastIdx[b]) g_scratch[OFF_HENC + i] = h;
}

__global__ void k_dec_combine(const float* __restrict__ dec_b) {
    int i = blockIdx.x * 256 + threadIdx.x;
    int b = i >> 10, j = i & (HH - 1);
    float g[4];
    #pragma unroll
    for (int q = 0; q < 4; q++) {
        int gi = b * GG + q * HH + j;
        float v = dec_b[q * HH + j];
        #pragma unroll
        for (int s = 0; s < NSPLIT; s++) v += g_scratch[OFF_PART + (size_t)s * BB * GG + gi];
        g[q] = v;
    }
    float c = g_scratch[OFF_DECC + i];
    c = sigm(g[1]) * c + sigm(g[0]) * tanhf(g[2]);
    g_scratch[OFF_DECC + i] = c;
    g_scratch[OFF_DECA + (size_t)b * KD + EE + j] = sigm(g[3]) * tanhf(c);
}

__global__ void k_combine_tanh(int N, const float* __restrict__ bias,
                               size_t outOff, int ldo, int off) {
    int i = blockIdx.x * 256 + threadIdx.x;
    if (i >= BB * N) return;
    int b = i / N, j = i - b * N;
    float v = bias[j];
    #pragma unroll
    for (int s = 0; s < NSPLIT; s++) v += g_scratch[OFF_PART + (size_t)s * BB * N + i];
    g_scratch[outOff + (size_t)b * ldo + off + j] = tanhf(v);
}

__global__ void k_reduce(int t, const int* __restrict__ sent,
                         float* __restrict__ out, long long predOff) {
    __shared__ float smv[256];
    __shared__ int   smi[256];
    __shared__ float sm2[256];
    int b = blockIdx.x, tid = threadIdx.x;
    const float* row = out + ((size_t)b * TT + t) * VV;

    float mv = -3.4e38f; int mi = 0;
    for (int v = tid; v < VV; v += 256) {
        float x = row[v];
        if (x > mv) { mv = x; mi = v; }
    }
    smv[tid] = mv; smi[tid] = mi;
    __syncthreads();
    for (int o = 128; o; o >>= 1) {
        if (tid < o) {
            float xv = smv[tid + o]; int xi = smi[tid + o];
            if (xv > smv[tid] || (xv == smv[tid] && xi < smi[tid])) { smv[tid] = xv; smi[tid] = xi; }
        }
        __syncthreads();
    }
    float m = smv[0]; int amax = smi[0];
    __syncthreads();

    float s = 0.0f;
    for (int v = tid; v < VV; v += 256) s += expf(row[v] - m);
    sm2[tid] = s;
    __syncthreads();
    for (int o = 128; o; o >>= 1) { if (tid < o) sm2[tid] += sm2[tid + o]; __syncthreads(); }

    if (tid == 0) {
        float logZ = m + logf(sm2[0]);
        int tgt = sent[b * TT + t];
        g_scratch[OFF_NLL + b * TT + t] = (tgt != 0) ? (logZ - row[tgt]) : 0.0f;
        g_pred[b] = amax;
        if (predOff >= 0) out[predOff + b * TT + t] = (float)amax;
    }
}

__global__ void k_loss(float* __restrict__ out, long long lossOff) {
    __shared__ float sm[256];
    int tid = threadIdx.x;
    float s = 0.0f;
    for (int i = tid; i < BB * TT; i += 256) s += g_scratch[OFF_NLL + i];
    sm[tid] = s;
    __syncthreads();
    for (int o = 128; o; o >>= 1) { if (tid < o) sm[tid] += sm[tid + o]; __syncthreads(); }
    if (tid == 0 && lossOff >= 0) out[lossOff] = sm[0] / fmaxf(g_maskSum, 1.0f);
}

extern "C" void kernel_launch(void* const* d_in, const int* in_sizes, int n_in,
                              void* d_out, int out_size) {
    const int*   sent   = (const int*)  d_in[0];
    const float* W_emb  = (const float*)d_in[1];
    const float* enc_Wi = (const float*)d_in[2];
    const float* enc_Wh = (const float*)d_in[3];
    const float* enc_b  = (const float*)d_in[4];
    const float* dec_Wi = (const float*)d_in[5];
    const float* dec_Wh = (const float*)d_in[6];
    const float* dec_b  = (const float*)d_in[7];
    const float* Ws     = (const float*)d_in[8];
    const float* bs     = (const float*)d_in[9];
    const float* Wo     = (const float*)d_in[10];
    const float* bo     = (const float*)d_in[11];
    const float* Wc     = (const float*)d_in[12];
    const float* bc     = (const float*)d_in[13];
    const float* Wout   = (const float*)d_in[14];
    const float* bout   = (const float*)d_in[15];
    float* out = (float*)d_out;

    float* scr = nullptr;
    cudaGetSymbolAddress((void**)&scr, g_scratch);

    long long need = (long long)BB * TT * VV;
    long long predOff = ((long long)out_size >= need + BB * TT) ? need : -1;
    long long lossOff = ((long long)out_size >= need + BB * TT + 1) ? need + BB * TT : -1;

    k_prep<<<1, 32>>>(sent);
    k_init<<<(BB * HH + 255) / 256, 256>>>();

    dim3 tb(32, 8);
    k_transpose<<<dim3(HH / 32, VV / 32), tb>>>(Wout,   scr + OFF_WOUT_T, VV, HH);
    k_transpose<<<dim3(EE / 32, GG / 32), tb>>>(enc_Wi, scr + OFF_ENCWI_T, GG, EE);
    k_transpose<<<dim3(HH / 32, GG / 32), tb>>>(enc_Wh, scr + OFF_ENCWH_T, GG, HH);
    k_transpose<<<dim3(EE / 32, GG / 32), tb>>>(dec_Wi, scr + OFF_DECW_T, GG, EE);
    k_transpose<<<dim3(HH / 32, GG / 32), tb>>>(dec_Wh, scr + OFF_DECW_T + (size_t)EE * GG, GG, HH);
    k_transpose<<<dim3(HH / 32, SS / 32), tb>>>(Ws,     scr + OFF_WS_T, SS, HH);
    k_transpose<<<dim3(HH / 32, SS / 32), tb>>>(Wo,     scr + OFF_WO_T, SS, HH);
    k_transpose<<<dim3(HH / 32, HH / 32), tb>>>(Wc,     scr + OFF_WC_T, HH, HH);

    k_gather_emb<<<BB * TT, 128>>>(sent, W_emb);

    // encoder x-part for all (b,t), enc_b folded as bias
    k_gemm32<<<dim3(GG / 256, (BB * TT) / 32, 1), 256>>>(
        scr + OFF_EMB, EE, scr + OFF_ENCWI_T, GG,
        scr + OFF_ENCX, GG, EE, enc_b, 0);

    // encoder recurrence
    for (int t = 0; t < TT; t++) {
        k_gemm32<<<dim3(GG / 256, 1, NSPLIT), 256>>>(
            scr + OFF_ENCH, HH, scr + OFF_ENCWH_T, GG,
            scr + OFF_PART, GG, HH / NSPLIT, nullptr, (long long)BB * GG);
        k_enc_combine<<<(BB * HH) / 256, 256>>>(t);
    }

    // bottleneck
    k_gemm32<<<dim3(SS / 256, 1, NSPLIT), 256>>>(
        scr + OFF_HENC, HH, scr + OFF_WS_T, SS,
        scr + OFF_PART, SS, HH / NSPLIT, nullptr, (long long)BB * SS);
    k_combine_tanh<<<(BB * SS + 255) / 256, 256>>>(SS, bs, OFF_CAT, HH, 0);

    k_gemm32<<<dim3(SS / 256, 1, NSPLIT), 256>>>(
        scr + OFF_HENC, HH, scr + OFF_WO_T, SS,
        scr + OFF_PART, SS, HH / NSPLIT, nullptr, (long long)BB * SS);
    k_combine_tanh<<<(BB * SS + 255) / 256, 256>>>(SS, bo, OFF_CAT, HH, SS);

    k_gemm32<<<dim3(HH / 256, 1, NSPLIT), 256>>>(
        scr + OFF_CAT, HH, scr + OFF_WC_T, HH,
        scr + OFF_PART, HH, HH / NSPLIT, nullptr, (long long)BB * HH);
    k_combine_tanh<<<(BB * HH + 255) / 256, 256>>>(HH, bc, OFF_DECA, KD, EE);

    // decoder: greedy autoregressive
    for (int t = 0; t < TT; t++) {
        k_gather_pred<<<BB, 128>>>(W_emb);
        k_gemm32<<<dim3(GG / 256, 1, NSPLIT), 256>>>(
            scr + OFF_DECA, KD, scr + OFF_DECW_T, GG,
            scr + OFF_PART, GG, KD / NSPLIT, nullptr, (long long)BB * GG);
        k_dec_combine<<<(BB * HH) / 256, 256>>>(dec_b);
        // logits_t = h @ Wout^T + bout  ->  out[b][t][:]
        k_gemm32<<<dim3(VV / 256, 1, 1), 256>>>(
            scr + OFF_DECA + EE, KD, scr + OFF_WOUT_T, VV,
            out + (size_t)t * VV, (long long)TT * VV, HH, bout, 0);
        k_reduce<<<BB, 256>>>(t, sent, out, predOff);
    }

    k_loss<<<1, 256>>>(out, lossOff);
}

// round 13
// speedup vs baseline: 2.0460x; 2.0460x over previous
#include <cuda_runtime.h>
#include <cstdint>

#define BB 32
#define TT 64
#define VV 32000
#define EE 512
#define HH 1024
#define GG 4096
#define SS 512
#define KD 1536
#define NSPLIT 8

typedef unsigned long long u64;

// ---- scratch layout (floats) ----
constexpr size_t OFF_WOUT_T  = 0;                                   // [1024][32000]
constexpr size_t OFF_ENCWI_T = OFF_WOUT_T  + (size_t)HH * VV;       // [512][4096]
constexpr size_t OFF_ENCWH_T = OFF_ENCWI_T + (size_t)EE * GG;       // [1024][4096]
constexpr size_t OFF_DECW_T  = OFF_ENCWH_T + (size_t)HH * GG;       // [1536][4096]
constexpr size_t OFF_WS_T    = OFF_DECW_T  + (size_t)KD * GG;       // [1024][512]
constexpr size_t OFF_WO_T    = OFF_WS_T    + (size_t)HH * SS;
constexpr size_t OFF_WC_T    = OFF_WO_T    + (size_t)HH * SS;       // [1024][1024]
constexpr size_t OFF_EMB     = OFF_WC_T    + (size_t)HH * HH;       // [2048][512]
constexpr size_t OFF_ENCX    = OFF_EMB     + (size_t)BB * TT * EE;  // [2048][4096]
constexpr size_t OFF_PART    = OFF_ENCX    + (size_t)BB * TT * GG;  // [8][32][4096]
constexpr size_t OFF_ENCH    = OFF_PART    + (size_t)NSPLIT * BB * GG;
constexpr size_t OFF_ENCC    = OFF_ENCH    + (size_t)BB * HH;
constexpr size_t OFF_DECA    = OFF_ENCC    + (size_t)BB * HH;       // [32][1536] = [emb|h]
constexpr size_t OFF_DECC    = OFF_DECA    + (size_t)BB * KD;
constexpr size_t OFF_HENC    = OFF_DECC    + (size_t)BB * HH;
constexpr size_t OFF_CAT     = OFF_HENC    + (size_t)BB * HH;       // [32][1024]
constexpr size_t OFF_NLL     = OFF_CAT     + (size_t)BB * HH;
constexpr size_t SCRATCH_SZ  = OFF_NLL     + (size_t)BB * TT;

__device__ __align__(16) float g_scratch[SCRATCH_SZ];
__device__ int   g_pred[BB];
__device__ int   g_lastIdx[BB];
__device__ float g_maskSum;

__device__ __forceinline__ u64 fma2(u64 a, u64 b, u64 c) {
    u64 d; asm("fma.rn.f32x2 %0, %1, %2, %3;" : "=l"(d) : "l"(a), "l"(b), "l"(c)); return d;
}
__device__ __forceinline__ u64 pack2(float x, float y) {
    u64 d; asm("mov.b64 %0, {%1, %2};" : "=l"(d) : "f"(x), "f"(y)); return d;
}
__device__ __forceinline__ float2 unpack2(u64 v) {
    float2 r; asm("mov.b64 {%0, %1}, %2;" : "=f"(r.x), "=f"(r.y) : "l"(v)); return r;
}
__device__ __forceinline__ float sigm(float x) { return 1.0f / (1.0f + expf(-x)); }

__global__ void k_prep(const int* __restrict__ s) {
    int b = threadIdx.x;
    int cnt = 0;
    #pragma unroll
    for (int t = 0; t < TT; t++) cnt += (s[b * TT + t] != 0);
    int li = cnt - 1; if (li < 0) li = 0; if (li > TT - 1) li = TT - 1;
    g_lastIdx[b] = li;
    g_pred[b] = 1;
    int tot = cnt;
    #pragma unroll
    for (int o = 16; o; o >>= 1) tot += __shfl_down_sync(0xffffffffu, tot, o);
    if (b == 0) g_maskSum = (float)tot;
}

__global__ void k_init() {
    int i = blockIdx.x * 256 + threadIdx.x;
    if (i < BB * HH) {
        g_scratch[OFF_ENCH + i] = 0.0f;
        g_scratch[OFF_ENCC + i] = 0.0f;
        g_scratch[OFF_DECC + i] = 0.0f;
    }
}

// in[R][C] -> out[C][R]; dims multiples of 32
__global__ void k_transpose(const float* __restrict__ in, float* __restrict__ out, int R, int C) {
    __shared__ float tile[32][33];
    int c0 = blockIdx.x * 32, r0 = blockIdx.y * 32;
    int x = threadIdx.x, y = threadIdx.y;
    #pragma unroll
    for (int j = 0; j < 32; j += 8)
        tile[y + j][x] = in[(size_t)(r0 + y + j) * C + c0 + x];
    __syncthreads();
    #pragma unroll
    for (int j = 0; j < 32; j += 8)
        out[(size_t)(c0 + y + j) * R + r0 + x] = tile[x][y + j];
}

__global__ void k_gather_emb(const int* __restrict__ s, const float* __restrict__ Wemb) {
    int r = blockIdx.x;
    const float4* src = (const float4*)(Wemb + (size_t)s[r] * EE);
    float4* dst = (float4*)(g_scratch + OFF_EMB + (size_t)r * EE);
    dst[threadIdx.x] = src[threadIdx.x];
}

__global__ void k_gather_pred(const float* __restrict__ Wemb) {
    int b = blockIdx.x;
    const float4* src = (const float4*)(Wemb + (size_t)g_pred[b] * EE);
    float4* dst = (float4*)(g_scratch + OFF_DECA + (size_t)b * KD);
    dst[threadIdx.x] = src[threadIdx.x];
}

// out[m][n] = sum_k A[m][k]*Bt[k][n] (+bias). grid: (N/256, Mtiles, splits)
// Full-tile register prefetch (B: 32 vals, A: next float4) one kt-tile ahead.
__global__ void __launch_bounds__(256) k_gemm32(
    const float* __restrict__ A, int lda,
    const float* __restrict__ Bt, int ldb,
    float* __restrict__ out, long long ldo,
    int kLen, const float* __restrict__ bias, long long splitPitch)
{
    __shared__ __align__(16) float Asm[32][40];
    const int tid = threadIdx.x;
    const int n = blockIdx.x * 256 + tid;
    A   += (size_t)blockIdx.y * 32 * lda;
    out += (size_t)blockIdx.y * 32 * ldo + (size_t)blockIdx.z * splitPitch;
    const int kbeg = blockIdx.z * kLen;

    u64 acc[16];
    #pragma unroll
    for (int i = 0; i < 16; i++) acc[i] = 0ull;

    const int m  = tid & 31;
    const int kq = (tid >> 5) << 2;

    // preload tile 0 (B into 32 regs, A fragment)
    float bv[32];
    {
        const float* bp = Bt + (size_t)kbeg * ldb + n;
        #pragma unroll
        for (int j = 0; j < 32; j++) bv[j] = bp[(size_t)j * ldb];
    }
    float4 av = *(const float4*)(A + (size_t)m * lda + (kbeg + kq));

    for (int kt = 0; kt < kLen; kt += 32) {
        __syncthreads();
        Asm[kq + 0][m] = av.x; Asm[kq + 1][m] = av.y;
        Asm[kq + 2][m] = av.z; Asm[kq + 3][m] = av.w;
        __syncthreads();

        float bn[32];
        float4 an;
        const bool more = (kt + 32) < kLen;
        if (more) {
            const float* bp = Bt + (size_t)(kbeg + kt + 32) * ldb + n;
            #pragma unroll
            for (int j = 0; j < 32; j++) bn[j] = bp[(size_t)j * ldb];
            an = *(const float4*)(A + (size_t)m * lda + (kbeg + kt + 32 + kq));
        }

        #pragma unroll
        for (int kk = 0; kk < 32; kk++) {
            u64 b2 = pack2(bv[kk], bv[kk]);
            const ulonglong2* ar = (const ulonglong2*)(&Asm[kk][0]);
            #pragma unroll
            for (int q = 0; q < 8; q++) {
                ulonglong2 a2 = ar[q];
                acc[2 * q]     = fma2(a2.x, b2, acc[2 * q]);
                acc[2 * q + 1] = fma2(a2.y, b2, acc[2 * q + 1]);
            }
        }
        if (more) {
            #pragma unroll
            for (int j = 0; j < 32; j++) bv[j] = bn[j];
            av = an;
        }
    }
    float bvadd = bias ? bias[n] : 0.0f;
    #pragma unroll
    for (int mp = 0; mp < 16; mp++) {
        float2 r = unpack2(acc[mp]);
        out[(size_t)(2 * mp)     * ldo + n] = r.x + bvadd;
        out[(size_t)(2 * mp + 1) * ldo + n] = r.y + bvadd;
    }
}

__global__ void k_enc_combine(int t) {
    int i = blockIdx.x * 256 + threadIdx.x;
    int b = i >> 10, j = i & (HH - 1);
    float g[4];
    #pragma unroll
    for (int q = 0; q < 4; q++) {
        int gi = b * GG + q * HH + j;
        float v = g_scratch[OFF_ENCX + (size_t)(b * TT + t) * GG + q * HH + j];
        #pragma unroll
        for (int s = 0; s < NSPLIT; s++) v += g_scratch[OFF_PART + (size_t)s * BB * GG + gi];
        g[q] = v;
    }
    float c = g_scratch[OFF_ENCC + i];
    c = sigm(g[1]) * c + sigm(g[0]) * tanhf(g[2]);
    g_scratch[OFF_ENCC + i] = c;
    float h = sigm(g[3]) * tanhf(c);
    g_scratch[OFF_ENCH + i] = h;
    if (t == g_lastIdx[b]) g_scratch[OFF_HENC + i] = h;
}

__global__ void k_dec_combine(const float* __restrict__ dec_b) {
    int i = blockIdx.x * 256 + threadIdx.x;
    int b = i >> 10, j = i & (HH - 1);
    float g[4];
    #pragma unroll
    for (int q = 0; q < 4; q++) {
        int gi = b * GG + q * HH + j;
        float v = dec_b[q * HH + j];
        #pragma unroll
        for (int s = 0; s < NSPLIT; s++) v += g_scratch[OFF_PART + (size_t)s * BB * GG + gi];
        g[q] = v;
    }
    float c = g_scratch[OFF_DECC + i];
    c = sigm(g[1]) * c + sigm(g[0]) * tanhf(g[2]);
    g_scratch[OFF_DECC + i] = c;
    g_scratch[OFF_DECA + (size_t)b * KD + EE + j] = sigm(g[3]) * tanhf(c);
}

__global__ void k_combine_tanh(int N, const float* __restrict__ bias,
                               size_t outOff, int ldo, int off) {
    int i = blockIdx.x * 256 + threadIdx.x;
    if (i >= BB * N) return;
    int b = i / N, j = i - b * N;
    float v = bias[j];
    #pragma unroll
    for (int s = 0; s < NSPLIT; s++) v += g_scratch[OFF_PART + (size_t)s * BB * N + i];
    g_scratch[outOff + (size_t)b * ldo + off + j] = tanhf(v);
}

// argmax + logsumexp + NLL; feeds pred back AND gathers next embedding (fused)
__global__ void k_reduce(int t, const int* __restrict__ sent,
                         const float* __restrict__ Wemb,
                         float* __restrict__ out, long long predOff) {
    __shared__ float smv[256];
    __shared__ int   smi[256];
    __shared__ float sm2[256];
    int b = blockIdx.x, tid = threadIdx.x;
    const float* row = out + ((size_t)b * TT + t) * VV;

    float mv = -3.4e38f; int mi = 0;
    for (int v = tid; v < VV; v += 256) {
        float x = row[v];
        if (x > mv) { mv = x; mi = v; }
    }
    smv[tid] = mv; smi[tid] = mi;
    __syncthreads();
    for (int o = 128; o; o >>= 1) {
        if (tid < o) {
            float xv = smv[tid + o]; int xi = smi[tid + o];
            if (xv > smv[tid] || (xv == smv[tid] && xi < smi[tid])) { smv[tid] = xv; smi[tid] = xi; }
        }
        __syncthreads();
    }
    float m = smv[0]; int amax = smi[0];
    __syncthreads();

    float s = 0.0f;
    for (int v = tid; v < VV; v += 256) s += expf(row[v] - m);
    sm2[tid] = s;
    __syncthreads();
    for (int o = 128; o; o >>= 1) { if (tid < o) sm2[tid] += sm2[tid + o]; __syncthreads(); }

    if (tid == 0) {
        float logZ = m + logf(sm2[0]);
        int tgt = sent[b * TT + t];
        g_scratch[OFF_NLL + b * TT + t] = (tgt != 0) ? (logZ - row[tgt]) : 0.0f;
        g_pred[b] = amax;
        if (predOff >= 0) out[predOff + b * TT + t] = (float)amax;
    }
    // fused gather of next-step embedding: W_emb[amax] -> DECA[b][0:512]
    const float2* src = (const float2*)(Wemb + (size_t)amax * EE);
    float2* dst = (float2*)(g_scratch + OFF_DECA + (size_t)b * KD);
    dst[tid] = src[tid];   // 256 threads * float2 = 512 floats
}

__global__ void k_loss(float* __restrict__ out, long long lossOff) {
    __shared__ float sm[256];
    int tid = threadIdx.x;
    float s = 0.0f;
    for (int i = tid; i < BB * TT; i += 256) s += g_scratch[OFF_NLL + i];
    sm[tid] = s;
    __syncthreads();
    for (int o = 128; o; o >>= 1) { if (tid < o) sm[tid] += sm[tid + o]; __syncthreads(); }
    if (tid == 0 && lossOff >= 0) out[lossOff] = sm[0] / fmaxf(g_maskSum, 1.0f);
}

extern "C" void kernel_launch(void* const* d_in, const int* in_sizes, int n_in,
                              void* d_out, int out_size) {
    const int*   sent   = (const int*)  d_in[0];
    const float* W_emb  = (const float*)d_in[1];
    const float* enc_Wi = (const float*)d_in[2];
    const float* enc_Wh = (const float*)d_in[3];
    const float* enc_b  = (const float*)d_in[4];
    const float* dec_Wi = (const float*)d_in[5];
    const float* dec_Wh = (const float*)d_in[6];
    const float* dec_b  = (const float*)d_in[7];
    const float* Ws     = (const float*)d_in[8];
    const float* bs     = (const float*)d_in[9];
    const float* Wo     = (const float*)d_in[10];
    const float* bo     = (const float*)d_in[11];
    const float* Wc     = (const float*)d_in[12];
    const float* bc     = (const float*)d_in[13];
    const float* Wout   = (const float*)d_in[14];
    const float* bout   = (const float*)d_in[15];
    float* out = (float*)d_out;

    float* scr = nullptr;
    cudaGetSymbolAddress((void**)&scr, g_scratch);

    long long need = (long long)BB * TT * VV;
    long long predOff = ((long long)out_size >= need + BB * TT) ? need : -1;
    long long lossOff = ((long long)out_size >= need + BB * TT + 1) ? need + BB * TT : -1;

    dim3 tb(32, 8);

    // Launch order chosen so ncu (-s 5 -c 1) captures the encX k_gemm32 (6th launch).
    k_prep<<<1, 32>>>(sent);                                             // 1
    k_init<<<(BB * HH + 255) / 256, 256>>>();                            // 2
    k_gather_emb<<<BB * TT, 128>>>(sent, W_emb);                         // 3
    k_transpose<<<dim3(EE / 32, GG / 32), tb>>>(enc_Wi, scr + OFF_ENCWI_T, GG, EE);   // 4
    k_transpose<<<dim3(HH / 32, VV / 32), tb>>>(Wout,   scr + OFF_WOUT_T, VV, HH);    // 5
    // encoder x-part for all (b,t), enc_b folded as bias                // 6 <- profiled
    k_gemm32<<<dim3(GG / 256, (BB * TT) / 32, 1), 256>>>(
        scr + OFF_EMB, EE, scr + OFF_ENCWI_T, GG,
        scr + OFF_ENCX, GG, EE, enc_b, 0);

    k_transpose<<<dim3(HH / 32, GG / 32), tb>>>(enc_Wh, scr + OFF_ENCWH_T, GG, HH);
    k_transpose<<<dim3(EE / 32, GG / 32), tb>>>(dec_Wi, scr + OFF_DECW_T, GG, EE);
    k_transpose<<<dim3(HH / 32, GG / 32), tb>>>(dec_Wh, scr + OFF_DECW_T + (size_t)EE * GG, GG, HH);
    k_transpose<<<dim3(HH / 32, SS / 32), tb>>>(Ws,     scr + OFF_WS_T, SS, HH);
    k_transpose<<<dim3(HH / 32, SS / 32), tb>>>(Wo,     scr + OFF_WO_T, SS, HH);
    k_transpose<<<dim3(HH / 32, HH / 32), tb>>>(Wc,     scr + OFF_WC_T, HH, HH);

    // encoder recurrence
    for (int t = 0; t < TT; t++) {
        k_gemm32<<<dim3(GG / 256, 1, NSPLIT), 256>>>(
            scr + OFF_ENCH, HH, scr + OFF_ENCWH_T, GG,
            scr + OFF_PART, GG, HH / NSPLIT, nullptr, (long long)BB * GG);
        k_enc_combine<<<(BB * HH) / 256, 256>>>(t);
    }

    // bottleneck
    k_gemm32<<<dim3(SS / 256, 1, NSPLIT), 256>>>(
        scr + OFF_HENC, HH, scr + OFF_WS_T, SS,
        scr + OFF_PART, SS, HH / NSPLIT, nullptr, (long long)BB * SS);
    k_combine_tanh<<<(BB * SS + 255) / 256, 256>>>(SS, bs, OFF_CAT, HH, 0);

    k_gemm32<<<dim3(SS / 256, 1, NSPLIT), 256>>>(
        scr + OFF_HENC, HH, scr + OFF_WO_T, SS,
        scr + OFF_PART, SS, HH / NSPLIT, nullptr, (long long)BB * SS);
    k_combine_tanh<<<(BB * SS + 255) / 256, 256>>>(SS, bo, OFF_CAT, HH, SS);

    k_gemm32<<<dim3(HH / 256, 1, NSPLIT), 256>>>(
        scr + OFF_CAT, HH, scr + OFF_WC_T, HH,
        scr + OFF_PART, HH, HH / NSPLIT, nullptr, (long long)BB * HH);
    k_combine_tanh<<<(BB * HH + 255) / 256, 256>>>(HH, bc, OFF_DECA, KD, EE);

    // initial decoder input: START embedding
    k_gather_pred<<<BB, 128>>>(W_emb);

    // decoder: greedy autoregressive
    for (int t = 0; t < TT; t++) {
        k_gemm32<<<dim3(GG / 256, 1, NSPLIT), 256>>>(
            scr + OFF_DECA, KD, scr + OFF_DECW_T, GG,
            scr + OFF_PART, GG, KD / NSPLIT, nullptr, (long long)BB * GG);
        k_dec_combine<<<(BB * HH) / 256, 256>>>(dec_b);
        // logits_t = h @ Wout^T + bout  ->  out[b][t][:]
        k_gemm32<<<dim3(VV / 256, 1, 1), 256>>>(
            scr + OFF_DECA + EE, KD, scr + OFF_WOUT_T, VV,
            out + (size_t)t * VV, (long long)TT * VV, HH, bout, 0);
        k_reduce<<<BB, 256>>>(t, sent, W_emb, out, predOff);
    }

    k_loss<<<1, 256>>>(out, lossOff);
}